// round 15
// baseline (speedup 1.0000x reference)
#include <cuda_runtime.h>
#include <cuda_fp16.h>
#include <math.h>
#include <stdint.h>

// ---------------- problem constants ----------------
#define N_TOK 196
#define BN_ROWS 3136
#define DIM 128
#define Q_ROWS 65536
#define INV_T 5.0f
#define M_PAD 3200          // 25 * 128
#define LO_SCALE 1024.0f
#define LO_DESCALE (1.0f/1024.0f)

#define POS_OFF 1
#define NEG_OFF (1 + BN_ROWS)

// ---------------- device globals (zero-init; pad rows stay 0) ----------------
__device__ float  g_q[BN_ROWS * DIM];
__device__ float  g_k[BN_ROWS * DIM];
__device__ __half g_qh[M_PAD * DIM];
__device__ __half g_ql[M_PAD * DIM];   // lo * 1024
__device__ __half g_uh[Q_ROWS * DIM];
__device__ __half g_ul[Q_ROWS * DIM];  // lo * 1024
__device__ float  g_rowsum[M_PAD];

// ---------------- helpers ----------------
__device__ __forceinline__ uint32_t split2(float a, float b, uint32_t& lo) {
    __half ha = __float2half_rn(a), hb = __float2half_rn(b);
    __half la = __float2half_rn((a - __half2float(ha)) * LO_SCALE);
    __half lb = __float2half_rn((b - __half2float(hb)) * LO_SCALE);
    __half2 h = __halves2half2(ha, hb);
    __half2 l = __halves2half2(la, lb);
    lo = *reinterpret_cast<uint32_t*>(&l);
    return *reinterpret_cast<uint32_t*>(&h);
}

__device__ __forceinline__ uint32_t smem_u32(const void* p) {
    uint32_t a;
    asm("{ .reg .u64 t; cvta.to.shared.u64 t, %1; cvt.u32.u64 %0, t; }" : "=r"(a) : "l"(p));
    return a;
}

#define MMA_F32(c, a, b) asm volatile( \
    "mma.sync.aligned.m16n8k16.row.col.f32.f16.f16.f32 " \
    "{%0,%1,%2,%3},{%4,%5,%6,%7},{%8,%9},{%0,%1,%2,%3};" \
    : "+f"((c)[0]), "+f"((c)[1]), "+f"((c)[2]), "+f"((c)[3]) \
    : "r"((a)[0]), "r"((a)[1]), "r"((a)[2]), "r"((a)[3]), \
      "r"((b)[0]), "r"((b)[1]))

#define MMA_F16(c, a, b) asm volatile( \
    "mma.sync.aligned.m16n8k16.row.col.f16.f16.f16.f16 " \
    "{%0,%1},{%2,%3,%4,%5},{%6,%7},{%0,%1};" \
    : "+r"((c)[0]), "+r"((c)[1]) \
    : "r"((a)[0]), "r"((a)[1]), "r"((a)[2]), "r"((a)[3]), \
      "r"((b)[0]), "r"((b)[1]))

#define LDSM_X4(r, addr) asm volatile( \
    "ldmatrix.sync.aligned.m8n8.x4.shared.b16 {%0,%1,%2,%3}, [%4];" \
    : "=r"((r)[0]), "=r"((r)[1]), "=r"((r)[2]), "=r"((r)[3]) : "r"(addr))

#define LDSM_X2(r, addr) asm volatile( \
    "ldmatrix.sync.aligned.m8n8.x2.shared.b16 {%0,%1}, [%2];" \
    : "=r"((r)[0]), "=r"((r)[1]) : "r"(addr))

#define CP_ASYNC16(dst, src) asm volatile( \
    "cp.async.cg.shared.global [%0], [%1], 16;" :: "r"(dst), "l"(src))

// ---------------------------------------------------------------------------
__global__ void zero_kernel() {
    int i = blockIdx.x * blockDim.x + threadIdx.x;
    if (i < M_PAD) g_rowsum[i] = 0.0f;
}

__global__ void norm_qk_kernel(const float* __restrict__ f1, const float* __restrict__ f2) {
    int w = (blockIdx.x * blockDim.x + threadIdx.x) >> 5;
    int lane = threadIdx.x & 31;
    if (w >= BN_ROWS) return;
    size_t base = (size_t)w * DIM;

    float4 v = ((const float4*)(f1 + base))[lane];
    float s = v.x * v.x + v.y * v.y + v.z * v.z + v.w * v.w;
    #pragma unroll
    for (int o = 16; o; o >>= 1) s += __shfl_xor_sync(0xffffffffu, s, o);
    float inv = 1.0f / sqrtf(fmaxf(s, 1e-24f));
    float4 r; r.x = v.x * inv; r.y = v.y * inv; r.z = v.z * inv; r.w = v.w * inv;
    ((float4*)(g_q + base))[lane] = r;
    uint32_t l0, l1;
    uint32_t h0 = split2(r.x, r.y, l0);
    uint32_t h1 = split2(r.z, r.w, l1);
    ((uint2*)(g_qh + base))[lane] = make_uint2(h0, h1);
    ((uint2*)(g_ql + base))[lane] = make_uint2(l0, l1);

    float4 u = ((const float4*)(f2 + base))[lane];
    float t = u.x * u.x + u.y * u.y + u.z * u.z + u.w * u.w;
    #pragma unroll
    for (int o = 16; o; o >>= 1) t += __shfl_xor_sync(0xffffffffu, t, o);
    float ik = 1.0f / sqrtf(fmaxf(t, 1e-24f));
    float4 rk; rk.x = u.x * ik; rk.y = u.y * ik; rk.z = u.z * ik; rk.w = u.w * ik;
    ((float4*)(g_k + base))[lane] = rk;
}

__global__ void norm_queue_kernel(const float* __restrict__ qin) {
    int w = (blockIdx.x * blockDim.x + threadIdx.x) >> 5;
    int lane = threadIdx.x & 31;
    if (w >= Q_ROWS) return;
    size_t base = (size_t)w * DIM;
    float4 v = ((const float4*)(qin + base))[lane];
    float s = v.x * v.x + v.y * v.y + v.z * v.z + v.w * v.w;
    #pragma unroll
    for (int o = 16; o; o >>= 1) s += __shfl_xor_sync(0xffffffffu, s, o);
    float inv = 1.0f / sqrtf(fmaxf(s, 1e-24f));
    uint32_t l0, l1;
    uint32_t h0 = split2(v.x * inv, v.y * inv, l0);
    uint32_t h1 = split2(v.z * inv, v.w * inv, l1);
    ((uint2*)(g_uh + base))[lane] = make_uint2(h0, h1);
    ((uint2*)(g_ul + base))[lane] = make_uint2(l0, l1);
}

// pos: one warp per query, 4 keys per iteration (392-block version).
__global__ void pos_kernel(float* __restrict__ out_pos) {
    int w = (blockIdx.x * blockDim.x + threadIdx.x) >> 5;
    int lane = threadIdx.x & 31;
    if (w >= BN_ROWS) return;
    int b = w / N_TOK;
    float4 qv = ((const float4*)(g_q + (size_t)w * DIM))[lane];
    const float4* kb = (const float4*)(g_k + (size_t)b * N_TOK * DIM);
    float best = -1e30f;
    for (int m = 0; m < N_TOK; m += 4) {
        const float4* p = kb + (size_t)m * 32;
        float4 a = p[lane], c = p[32 + lane], e = p[64 + lane], f = p[96 + lane];
        float d0 = qv.x * a.x + qv.y * a.y + qv.z * a.z + qv.w * a.w;
        float d1 = qv.x * c.x + qv.y * c.y + qv.z * c.z + qv.w * c.w;
        float d2 = qv.x * e.x + qv.y * e.y + qv.z * e.z + qv.w * e.w;
        float d3 = qv.x * f.x + qv.y * f.y + qv.z * f.z + qv.w * f.w;
        #pragma unroll
        for (int o = 16; o; o >>= 1) {
            d0 += __shfl_xor_sync(0xffffffffu, d0, o);
            d1 += __shfl_xor_sync(0xffffffffu, d1, o);
            d2 += __shfl_xor_sync(0xffffffffu, d2, o);
            d3 += __shfl_xor_sync(0xffffffffu, d3, o);
        }
        best = fmaxf(best, fmaxf(fmaxf(d0, d1), fmaxf(d2, d3)));
    }
    if (lane == 0) out_pos[w] = best * INV_T;
}

// ---------------------------------------------------------------------------
// neg GEMM: R6 scaffold (128x128 block, 8 warps 2x4, warp tile 64x32, BK=64
// fills, SW-swizzled smem, direct __stcs epilogue). Mixed precision:
//   Ahi*Bhi -> f32 acc (rt16); Ahi*Blo' + Alo'*Bhi -> shared f16 acc (rt8).
// KEY: outer jh loop processes the warp's j-range in 2 halves, each with its
// own K sweep (smem refilled). Live accumulators halve: accH 32 + accX 16 +
// frags ~12 => ~90 regs, no spills.
#define ARR_BYTES (128 * 128)
#define SMEM_BYTES (4 * ARR_BYTES + 512)

__global__ __launch_bounds__(256, 2)
void gemm_neg_kernel(float* __restrict__ neg) {
    extern __shared__ __align__(1024) char smem[];
    uint32_t sb = smem_u32(smem);
    uint32_t sAh = sb;
    uint32_t sAl = sb + ARR_BYTES;
    uint32_t sBh = sb + 2 * ARR_BYTES;
    uint32_t sBl = sb + 3 * ARR_BYTES;
    float* srow = (float*)(smem + 4 * ARR_BYTES);

    int tid = threadIdx.x;
    int lane = tid & 31, wid = tid >> 5;
    int g = lane >> 2, tg = lane & 3;
    int warp_m = wid & 1, warp_n = wid >> 1;
    int m0 = blockIdx.y * 128;
    size_t n0 = (size_t)blockIdx.x * 128;

    int fr = tid >> 2;           // 0..63
    int fu0 = (tid & 3) << 1;    // 0,2,4,6

    int a_row = warp_m * 64 + (lane & 15);
    int a_ch = lane >> 4;
    uint32_t aAh_base = sAh + a_row * 128;
    uint32_t aAl_base = sAl + a_row * 128;
    int a_sw = a_row & 7;
    int b_row = warp_n * 32 + (lane & 7);
    int b_ch = (lane >> 3) & 1;
    uint32_t aBh_base = sBh + b_row * 128;
    uint32_t aBl_base = sBl + b_row * 128;
    int b_sw = b_row & 7;

    for (int i = tid; i < 128; i += 256) srow[i] = 0.0f;

    #pragma unroll 1
    for (int jh = 0; jh < 2; jh++) {
        float    accH[4][2][4];
        uint32_t accX[4][2][2];
        #pragma unroll
        for (int i = 0; i < 4; i++)
            #pragma unroll
            for (int j2 = 0; j2 < 2; j2++) {
                accH[i][j2][0] = accH[i][j2][1] = accH[i][j2][2] = accH[i][j2][3] = 0.0f;
                accX[i][j2][0] = accX[i][j2][1] = 0u;
            }

        #pragma unroll
        for (int ph = 0; ph < 2; ph++) {
            int k0 = ph * 64;
            #pragma unroll
            for (int rr = 0; rr < 2; rr++) {
                int row = fr + rr * 64;
                #pragma unroll
                for (int uu = 0; uu < 2; uu++) {
                    int u = fu0 + uu;
                    uint32_t doff = row * 128 + ((u ^ (row & 7)) << 4);
                    CP_ASYNC16(sAh + doff, g_qh + (size_t)(m0 + row) * DIM + k0 + u * 8);
                    CP_ASYNC16(sAl + doff, g_ql + (size_t)(m0 + row) * DIM + k0 + u * 8);
                    CP_ASYNC16(sBh + doff, g_uh + (n0 + row) * DIM + k0 + u * 8);
                    CP_ASYNC16(sBl + doff, g_ul + (n0 + row) * DIM + k0 + u * 8);
                }
            }
            asm volatile("cp.async.commit_group;" ::: "memory");
            asm volatile("cp.async.wait_group 0;" ::: "memory");
            __syncthreads();

            #pragma unroll
            for (int s = 0; s < 4; s++) {
                uint32_t Bh[2][2], Bl[2][2];
                #pragma unroll
                for (int j2 = 0; j2 < 2; j2++) {
                    int j = jh * 2 + j2;
                    int ch = (2 * s + b_ch) ^ b_sw;
                    uint32_t boff = j * 8 * 128 + (ch << 4);
                    LDSM_X2(Bh[j2], aBh_base + boff);
                    LDSM_X2(Bl[j2], aBl_base + boff);
                }
                #pragma unroll
                for (int i = 0; i < 4; i++) {
                    int ch = (2 * s + a_ch) ^ a_sw;
                    uint32_t aoff = i * 16 * 128 + (ch << 4);
                    uint32_t Af[4];
                    LDSM_X4(Af, aAh_base + aoff);      // A hi
                    #pragma unroll
                    for (int j2 = 0; j2 < 2; j2++) MMA_F32(accH[i][j2], Af, Bh[j2]);
                    #pragma unroll
                    for (int j2 = 0; j2 < 2; j2++) MMA_F16(accX[i][j2], Af, Bl[j2]);
                    LDSM_X4(Af, aAl_base + aoff);      // A lo'
                    #pragma unroll
                    for (int j2 = 0; j2 < 2; j2++) MMA_F16(accX[i][j2], Af, Bh[j2]);
                }
            }
            __syncthreads();
        }

        // ---- epilogue for this j-half: combine, scale, store, expsum ----
        #pragma unroll
        for (int i = 0; i < 4; i++) {
            #pragma unroll
            for (int h = 0; h < 2; h++) {
                int rl = warp_m * 64 + i * 16 + g + h * 8;
                int gm = m0 + rl;
                if (gm < BN_ROWS) {
                    float* rp = neg + (size_t)gm * Q_ROWS + n0 + warp_n * 32 + tg * 2;
                    float es = 0.0f;
                    #pragma unroll
                    for (int j2 = 0; j2 < 2; j2++) {
                        int j = jh * 2 + j2;
                        float2 fx = __half22float2(*(const __half2*)&accX[i][j2][h]);
                        float v0 = fmaf(fx.x, LO_DESCALE, accH[i][j2][h * 2]) * INV_T;
                        float v1 = fmaf(fx.y, LO_DESCALE, accH[i][j2][h * 2 + 1]) * INV_T;
                        __stcs(rp + j * 8, v0);
                        __stcs(rp + j * 8 + 1, v1);
                        es += __expf(v0) + __expf(v1);
                    }
                    atomicAdd(&srow[rl], es);
                }
            }
        }
    }

    __syncthreads();
    for (int i = tid; i < 128; i += 256) {
        int gm = m0 + i;
        if (gm < BN_ROWS) atomicAdd(&g_rowsum[gm], srow[i]);
    }
}

// ---------------------------------------------------------------------------
__global__ void loss_kernel(const float* __restrict__ pos, float* __restrict__ out_loss) {
    __shared__ float sred[1024];
    float acc = 0.0f;
    for (int i = threadIdx.x; i < BN_ROWS; i += 1024) {
        float p = pos[i];
        acc += logf(g_rowsum[i] + expf(p)) - p;
    }
    sred[threadIdx.x] = acc;
    __syncthreads();
    for (int s = 512; s; s >>= 1) {
        if (threadIdx.x < s) sred[threadIdx.x] += sred[threadIdx.x + s];
        __syncthreads();
    }
    if (threadIdx.x == 0) out_loss[0] = sred[0] / (float)BN_ROWS;
}

// ---------------------------------------------------------------------------
extern "C" void kernel_launch(void* const* d_in, const int* in_sizes, int n_in,
                              void* d_out, int out_size) {
    const float* f1 = (const float*)d_in[0];
    const float* f2 = (const float*)d_in[1];
    const float* qu = (const float*)d_in[4];
    float* out = (float*)d_out;

    cudaFuncSetAttribute(gemm_neg_kernel, cudaFuncAttributeMaxDynamicSharedMemorySize, SMEM_BYTES);

    // gemm launched in the ncu-profiled slot.
    zero_kernel<<<7, 512>>>();
    norm_qk_kernel<<<BN_ROWS / 8, 256>>>(f1, f2);
    norm_queue_kernel<<<Q_ROWS / 8, 256>>>(qu);
    dim3 grid(Q_ROWS / 128, M_PAD / 128);   // (512, 25)
    gemm_neg_kernel<<<grid, 256, SMEM_BYTES>>>(out + NEG_OFF);
    pos_kernel<<<BN_ROWS / 8, 256>>>(out + POS_OFF);
    loss_kernel<<<1, 1024>>>(out + POS_OFF, out);
}

// round 17
// speedup vs baseline: 1.7825x; 1.7825x over previous
#include <cuda_runtime.h>
#include <cuda_fp16.h>
#include <math.h>
#include <stdint.h>

// ---------------- problem constants ----------------
#define N_TOK 196
#define BN_ROWS 3136
#define DIM 128
#define Q_ROWS 65536
#define INV_T 5.0f
#define M_PAD 3200          // 25 * 128

#define POS_OFF 1
#define NEG_OFF (1 + BN_ROWS)

// ---------------- device globals (zero-init; pad rows stay 0) ----------------
__device__ float  g_q[BN_ROWS * DIM];
__device__ float  g_k[BN_ROWS * DIM];
__device__ __half g_qh[M_PAD * DIM];
__device__ __half g_uh[Q_ROWS * DIM];
__device__ float  g_rowsum[M_PAD];

// ---------------- helpers ----------------
__device__ __forceinline__ uint32_t pack_h2(float a, float b) {
    __half2 h = __halves2half2(__float2half_rn(a), __float2half_rn(b));
    return *reinterpret_cast<uint32_t*>(&h);
}

__device__ __forceinline__ uint32_t smem_u32(const void* p) {
    uint32_t a;
    asm("{ .reg .u64 t; cvta.to.shared.u64 t, %1; cvt.u32.u64 %0, t; }" : "=r"(a) : "l"(p));
    return a;
}

#define MMA_F32(c, a, b) asm volatile( \
    "mma.sync.aligned.m16n8k16.row.col.f32.f16.f16.f32 " \
    "{%0,%1,%2,%3},{%4,%5,%6,%7},{%8,%9},{%0,%1,%2,%3};" \
    : "+f"((c)[0]), "+f"((c)[1]), "+f"((c)[2]), "+f"((c)[3]) \
    : "r"((a)[0]), "r"((a)[1]), "r"((a)[2]), "r"((a)[3]), \
      "r"((b)[0]), "r"((b)[1]))

#define LDSM_X4(r, addr) asm volatile( \
    "ldmatrix.sync.aligned.m8n8.x4.shared.b16 {%0,%1,%2,%3}, [%4];" \
    : "=r"((r)[0]), "=r"((r)[1]), "=r"((r)[2]), "=r"((r)[3]) : "r"(addr))

#define LDSM_X2(r, addr) asm volatile( \
    "ldmatrix.sync.aligned.m8n8.x2.shared.b16 {%0,%1}, [%2];" \
    : "=r"((r)[0]), "=r"((r)[1]) : "r"(addr))

#define CP_ASYNC16(dst, src) asm volatile( \
    "cp.async.cg.shared.global [%0], [%1], 16;" :: "r"(dst), "l"(src))

// ---------------------------------------------------------------------------
__global__ void zero_kernel() {
    int i = blockIdx.x * blockDim.x + threadIdx.x;
    if (i < M_PAD) g_rowsum[i] = 0.0f;
}

__global__ void norm_qk_kernel(const float* __restrict__ f1, const float* __restrict__ f2) {
    int w = (blockIdx.x * blockDim.x + threadIdx.x) >> 5;
    int lane = threadIdx.x & 31;
    if (w >= BN_ROWS) return;
    size_t base = (size_t)w * DIM;

    float4 v = ((const float4*)(f1 + base))[lane];
    float s = v.x * v.x + v.y * v.y + v.z * v.z + v.w * v.w;
    #pragma unroll
    for (int o = 16; o; o >>= 1) s += __shfl_xor_sync(0xffffffffu, s, o);
    float inv = 1.0f / sqrtf(fmaxf(s, 1e-24f));
    float4 r; r.x = v.x * inv; r.y = v.y * inv; r.z = v.z * inv; r.w = v.w * inv;
    ((float4*)(g_q + base))[lane] = r;
    ((uint2*)(g_qh + base))[lane] = make_uint2(pack_h2(r.x, r.y), pack_h2(r.z, r.w));

    float4 u = ((const float4*)(f2 + base))[lane];
    float t = u.x * u.x + u.y * u.y + u.z * u.z + u.w * u.w;
    #pragma unroll
    for (int o = 16; o; o >>= 1) t += __shfl_xor_sync(0xffffffffu, t, o);
    float ik = 1.0f / sqrtf(fmaxf(t, 1e-24f));
    float4 rk; rk.x = u.x * ik; rk.y = u.y * ik; rk.z = u.z * ik; rk.w = u.w * ik;
    ((float4*)(g_k + base))[lane] = rk;
}

__global__ void norm_queue_kernel(const float* __restrict__ qin) {
    int w = (blockIdx.x * blockDim.x + threadIdx.x) >> 5;
    int lane = threadIdx.x & 31;
    if (w >= Q_ROWS) return;
    size_t base = (size_t)w * DIM;
    float4 v = ((const float4*)(qin + base))[lane];
    float s = v.x * v.x + v.y * v.y + v.z * v.z + v.w * v.w;
    #pragma unroll
    for (int o = 16; o; o >>= 1) s += __shfl_xor_sync(0xffffffffu, s, o);
    float inv = 1.0f / sqrtf(fmaxf(s, 1e-24f));
    ((uint2*)(g_uh + base))[lane] =
        make_uint2(pack_h2(v.x * inv, v.y * inv), pack_h2(v.z * inv, v.w * inv));
}

// pos: one warp per query, 4 keys per iteration (392-block version).
__global__ void pos_kernel(float* __restrict__ out_pos) {
    int w = (blockIdx.x * blockDim.x + threadIdx.x) >> 5;
    int lane = threadIdx.x & 31;
    if (w >= BN_ROWS) return;
    int b = w / N_TOK;
    float4 qv = ((const float4*)(g_q + (size_t)w * DIM))[lane];
    const float4* kb = (const float4*)(g_k + (size_t)b * N_TOK * DIM);
    float best = -1e30f;
    for (int m = 0; m < N_TOK; m += 4) {
        const float4* p = kb + (size_t)m * 32;
        float4 a = p[lane], c = p[32 + lane], e = p[64 + lane], f = p[96 + lane];
        float d0 = qv.x * a.x + qv.y * a.y + qv.z * a.z + qv.w * a.w;
        float d1 = qv.x * c.x + qv.y * c.y + qv.z * c.z + qv.w * c.w;
        float d2 = qv.x * e.x + qv.y * e.y + qv.z * e.z + qv.w * e.w;
        float d3 = qv.x * f.x + qv.y * f.y + qv.z * f.z + qv.w * f.w;
        #pragma unroll
        for (int o = 16; o; o >>= 1) {
            d0 += __shfl_xor_sync(0xffffffffu, d0, o);
            d1 += __shfl_xor_sync(0xffffffffu, d1, o);
            d2 += __shfl_xor_sync(0xffffffffu, d2, o);
            d3 += __shfl_xor_sync(0xffffffffu, d3, o);
        }
        best = fmaxf(best, fmaxf(fmaxf(d0, d1), fmaxf(d2, d3)));
    }
    if (lane == 0) out_pos[w] = best * INV_T;
}

// ---------------------------------------------------------------------------
// neg GEMM: R6 scaffold, single-term fp16 (hi only): 128x128 block, 8 warps
// (2x4), warp tile 64x32, BK=64 x 2 phases, SW-swizzled smem, cp.async fills,
// direct __stcs epilogue. 1/3 the MMAs of R6; fp32 accumulators.
#define ARR_BYTES (128 * 128)
#define SMEM_BYTES (2 * ARR_BYTES + 512)

__global__ __launch_bounds__(256, 2)
void gemm_neg_kernel(float* __restrict__ neg) {
    extern __shared__ __align__(1024) char smem[];
    uint32_t sb = smem_u32(smem);
    uint32_t sAh = sb;
    uint32_t sBh = sb + ARR_BYTES;
    float* srow = (float*)(smem + 2 * ARR_BYTES);

    int tid = threadIdx.x;
    int lane = tid & 31, wid = tid >> 5;
    int g = lane >> 2, tg = lane & 3;
    int warp_m = wid & 1, warp_n = wid >> 1;
    int m0 = blockIdx.y * 128;
    size_t n0 = (size_t)blockIdx.x * 128;

    int fr = tid >> 2;           // 0..63
    int fu0 = (tid & 3) << 1;    // 0,2,4,6

    int a_row = warp_m * 64 + (lane & 15);
    int a_ch = lane >> 4;
    uint32_t aAh_base = sAh + a_row * 128;
    int a_sw = a_row & 7;
    int b_row = warp_n * 32 + (lane & 7);
    int b_ch = (lane >> 3) & 1;
    uint32_t aBh_base = sBh + b_row * 128;
    int b_sw = b_row & 7;

    float acc[4][4][4];
    #pragma unroll
    for (int i = 0; i < 4; i++)
        #pragma unroll
        for (int j = 0; j < 4; j++)
            #pragma unroll
            for (int c = 0; c < 4; c++) acc[i][j][c] = 0.0f;

    #pragma unroll
    for (int ph = 0; ph < 2; ph++) {
        int k0 = ph * 64;
        #pragma unroll
        for (int rr = 0; rr < 2; rr++) {
            int row = fr + rr * 64;
            #pragma unroll
            for (int uu = 0; uu < 2; uu++) {
                int u = fu0 + uu;
                uint32_t doff = row * 128 + ((u ^ (row & 7)) << 4);
                CP_ASYNC16(sAh + doff, g_qh + (size_t)(m0 + row) * DIM + k0 + u * 8);
                CP_ASYNC16(sBh + doff, g_uh + (n0 + row) * DIM + k0 + u * 8);
            }
        }
        asm volatile("cp.async.commit_group;" ::: "memory");
        asm volatile("cp.async.wait_group 0;" ::: "memory");
        __syncthreads();

        #pragma unroll
        for (int s = 0; s < 4; s++) {
            uint32_t Bh[4][2];
            #pragma unroll
            for (int j = 0; j < 4; j++) {
                int ch = (2 * s + b_ch) ^ b_sw;
                LDSM_X2(Bh[j], aBh_base + j * 8 * 128 + (ch << 4));
            }
            #pragma unroll
            for (int i = 0; i < 4; i++) {
                int ch = (2 * s + a_ch) ^ a_sw;
                uint32_t Af[4];
                LDSM_X4(Af, aAh_base + i * 16 * 128 + (ch << 4));
                #pragma unroll
                for (int j = 0; j < 4; j++) MMA_F32(acc[i][j], Af, Bh[j]);
            }
        }
        if (ph == 0) __syncthreads();
    }

    // ---- epilogue: scale, direct scalar stores (neg base 4B-misaligned),
    // fused expf row sums.
    for (int i = tid; i < 128; i += 256) srow[i] = 0.0f;
    __syncthreads();

    #pragma unroll
    for (int i = 0; i < 4; i++) {
        #pragma unroll
        for (int h = 0; h < 2; h++) {
            int rl = warp_m * 64 + i * 16 + g + h * 8;
            int gm = m0 + rl;
            if (gm < BN_ROWS) {
                float* rp = neg + (size_t)gm * Q_ROWS + n0 + warp_n * 32 + tg * 2;
                float es = 0.0f;
                #pragma unroll
                for (int j = 0; j < 4; j++) {
                    float v0 = acc[i][j][h * 2] * INV_T;
                    float v1 = acc[i][j][h * 2 + 1] * INV_T;
                    __stcs(rp + j * 8, v0);
                    __stcs(rp + j * 8 + 1, v1);
                    es += __expf(v0) + __expf(v1);
                }
                atomicAdd(&srow[rl], es);
            }
        }
    }
    __syncthreads();
    for (int i = tid; i < 128; i += 256) {
        int gm = m0 + i;
        if (gm < BN_ROWS) atomicAdd(&g_rowsum[gm], srow[i]);
    }
}

// ---------------------------------------------------------------------------
__global__ void loss_kernel(const float* __restrict__ pos, float* __restrict__ out_loss) {
    __shared__ float sred[1024];
    float acc = 0.0f;
    for (int i = threadIdx.x; i < BN_ROWS; i += 1024) {
        float p = pos[i];
        acc += logf(g_rowsum[i] + expf(p)) - p;
    }
    sred[threadIdx.x] = acc;
    __syncthreads();
    for (int s = 512; s; s >>= 1) {
        if (threadIdx.x < s) sred[threadIdx.x] += sred[threadIdx.x + s];
        __syncthreads();
    }
    if (threadIdx.x == 0) out_loss[0] = sred[0] / (float)BN_ROWS;
}

// ---------------------------------------------------------------------------
extern "C" void kernel_launch(void* const* d_in, const int* in_sizes, int n_in,
                              void* d_out, int out_size) {
    const float* f1 = (const float*)d_in[0];
    const float* f2 = (const float*)d_in[1];
    const float* qu = (const float*)d_in[4];
    float* out = (float*)d_out;

    cudaFuncSetAttribute(gemm_neg_kernel, cudaFuncAttributeMaxDynamicSharedMemorySize, SMEM_BYTES);

    // gemm launched in the ncu-profiled slot.
    zero_kernel<<<7, 512>>>();
    norm_qk_kernel<<<BN_ROWS / 8, 256>>>(f1, f2);
    norm_queue_kernel<<<Q_ROWS / 8, 256>>>(qu);
    dim3 grid(Q_ROWS / 128, M_PAD / 128);   // (512, 25)
    gemm_neg_kernel<<<grid, 256, SMEM_BYTES>>>(out + NEG_OFF);
    pos_kernel<<<BN_ROWS / 8, 256>>>(out + POS_OFF);
    loss_kernel<<<1, 1024>>>(out + POS_OFF, out);
}